// round 5
// baseline (speedup 1.0000x reference)
#include <cuda_runtime.h>
#include <cstdint>

#define BB 4096
#define TT 512
#define IND 64
#define HH 10

// 335.5 MB scratch: permuted layout idx = bt*40 + j*4 + gate (0=i 1=f 2=g 3=o)
__device__ float xg_buf[(size_t)BB * TT * 40];

__device__ __forceinline__ void fma2(unsigned long long& d,
                                     unsigned long long a,
                                     unsigned long long b) {
    asm("fma.rn.f32x2 %0, %1, %2, %0;" : "+l"(d) : "l"(a), "l"(b));
}
#define PACK2(d, lo, hi) \
    asm("mov.b64 %0, {%1, %2};" : "=l"(d) : "f"(lo), "f"(hi))
#define UNPACK2(lo, hi, s) \
    asm("mov.b64 {%0, %1}, %2;" : "=f"(lo), "=f"(hi) : "l"(s))

// ---------------------------------------------------------------------------
// K1: [2M x 64] * [64 x 40] + bias.  256 threads, 128 rows/block.
// Thread tile: 4 rows x 5 gates (40 acc regs). f32x2 packed FMA.
// ---------------------------------------------------------------------------
__global__ __launch_bounds__(256, 3)
void input_proj_kernel(const float* __restrict__ x,
                       const float* __restrict__ W_ih,
                       const float* __restrict__ b_ih,
                       const float* __restrict__ b_hh,
                       int block0)
{
    __shared__ __align__(16) float4 xs[128][17];   // 128 rows x 16 f4 (+pad)
    __shared__ __align__(16) float4 ws[40][17];    // 40 gates x 16 f4 (+pad)

    const int tid = threadIdx.x;
    const size_t row0 = (size_t)(blockIdx.x + block0) * 128;

    const float4* x4 = (const float4*)(x + row0 * IND);
    #pragma unroll
    for (int i = tid; i < 2048; i += 256)
        xs[i >> 4][i & 15] = __ldcs(&x4[i]);
    const float4* w4 = (const float4*)W_ih;
    #pragma unroll
    for (int i = tid; i < 640; i += 256)
        ws[i >> 4][i & 15] = w4[i];
    __syncthreads();

    const int tx = tid & 7;          // gate group (5 gates)
    const int ty = tid >> 3;         // row group  (4 rows)
    const int g0 = tx * 5;
    const int r0 = ty * 4;

    float bsum[5];
    #pragma unroll
    for (int g = 0; g < 5; ++g)
        bsum[g] = b_ih[g0 + g] + b_hh[g0 + g];

    unsigned long long acc[4][5];
    #pragma unroll
    for (int r = 0; r < 4; ++r)
        #pragma unroll
        for (int g = 0; g < 5; ++g)
            acc[r][g] = 0ull;

    #pragma unroll 4
    for (int kc = 0; kc < 16; ++kc) {
        float4 wb[5];
        #pragma unroll
        for (int g = 0; g < 5; ++g) wb[g] = ws[g0 + g][kc];

        #pragma unroll
        for (int r = 0; r < 4; ++r) {
            float4 xv = xs[r0 + r][kc];
            const unsigned long long* xp = (const unsigned long long*)&xv;
            #pragma unroll
            for (int g = 0; g < 5; ++g) {
                const unsigned long long* wp = (const unsigned long long*)&wb[g];
                fma2(acc[r][g], xp[0], wp[0]);
                fma2(acc[r][g], xp[1], wp[1]);
            }
        }
    }

    // epilogue: reduce pairs, bias, permute to [j*4+gate], coalesced flush
    __syncthreads();
    float* osm = (float*)xs;    // stride 44 floats per row (16B-aligned rows)
    #pragma unroll
    for (int r = 0; r < 4; ++r) {
        #pragma unroll
        for (int g = 0; g < 5; ++g) {
            float lo, hi;
            UNPACK2(lo, hi, acc[r][g]);
            float v = lo + hi + bsum[g];
            int gg = g0 + g;
            int j  = gg % 10;
            int gi = gg / 10;
            osm[(r0 + r) * 44 + j * 4 + gi] = v;
        }
    }
    __syncthreads();

    float4* dst = (float4*)(xg_buf + row0 * 40);
    const float4* src4 = (const float4*)osm;
    #pragma unroll
    for (int i = tid; i < 1280; i += 256) {
        int rr = i / 10, c = i - rr * 10;
        __stcs(&dst[i], src4[rr * 11 + c]);
    }
}

// ---------------------------------------------------------------------------
// K2: recurrent scan. 3 batches/warp (lanes 0..29), unit j = lane%10.
// h exchanged via double-buffered smem; gates k-paired with f32x2.
// ---------------------------------------------------------------------------
__device__ __forceinline__ float sigm_fast(float x) {
    return __fdividef(1.0f, 1.0f + __expf(-x));
}
__device__ __forceinline__ float tanh_fast(float x) {
    return 1.0f - 2.0f * __fdividef(1.0f, 1.0f + __expf(2.0f * x));
}

#define K2_THREADS 64
#define K2_BATCH_PER_BLOCK 6

__global__ __launch_bounds__(K2_THREADS, 1)
void lstm_scan_kernel(const float* __restrict__ W_hh,
                      float* __restrict__ out)
{
    __shared__ __align__(8) float hsm[2][2][32];   // [buf][warp][slot]

    const int lane = threadIdx.x & 31;
    const int warp = threadIdx.x >> 5;
    int group = lane / 10;
    const bool active = (lane < 30);
    if (!active) group = 2;
    const int j = active ? (lane - group * 10) : 0;
    const int srcbase = group * 10;
    const int slot = active ? (srcbase + j) : lane;   // lanes 30/31 -> dummy slots

    const int b = blockIdx.x * K2_BATCH_PER_BLOCK + warp * 3 + group;
    const bool valid = active && (b < BB);
    const int b_eff = valid ? b : 0;

    // packed recurrent weights: (w[2p], w[2p+1]) per gate
    unsigned long long wI2[5], wF2[5], wG2[5], wO2[5];
    #pragma unroll
    for (int p = 0; p < 5; ++p) {
        PACK2(wI2[p], W_hh[(j)      * HH + 2 * p], W_hh[(j)      * HH + 2 * p + 1]);
        PACK2(wF2[p], W_hh[(j + 10) * HH + 2 * p], W_hh[(j + 10) * HH + 2 * p + 1]);
        PACK2(wG2[p], W_hh[(j + 20) * HH + 2 * p], W_hh[(j + 20) * HH + 2 * p + 1]);
        PACK2(wO2[p], W_hh[(j + 30) * HH + 2 * p], W_hh[(j + 30) * HH + 2 * p + 1]);
    }

    const float4* xgp = (const float4*)(xg_buf + (size_t)b_eff * TT * 40) + j;

    float4 pf[8];
    #pragma unroll
    for (int d = 0; d < 8; ++d)
        pf[d] = __ldcs(&xgp[(size_t)d * 10]);

    hsm[0][warp][slot] = 0.0f;          // h(-1) = 0
    __syncwarp();

    float h = 0.0f, c = 0.0f;
    float* outp = out + (size_t)b_eff * TT * HH + j;

    for (int t = 0; t < TT; t += 8) {
        #pragma unroll
        for (int u = 0; u < 8; ++u) {
            const int tt = t + u;
            float4 xv = pf[u];
            int tn = tt + 8;
            if (tn < TT)
                pf[u] = __ldcs(&xgp[(size_t)tn * 10]);

            // load h pairs of my batch from the current buffer
            const float* hb = &hsm[tt & 1][warp][srcbase];
            unsigned long long hp[5];
            #pragma unroll
            for (int p = 0; p < 5; ++p)
                hp[p] = *(const unsigned long long*)(hb + 2 * p);

            unsigned long long aI2, aF2, aG2, aO2;
            PACK2(aI2, xv.x, 0.0f);
            PACK2(aF2, xv.y, 0.0f);
            PACK2(aG2, xv.z, 0.0f);
            PACK2(aO2, xv.w, 0.0f);
            #pragma unroll
            for (int p = 0; p < 5; ++p) {
                fma2(aI2, hp[p], wI2[p]);
                fma2(aF2, hp[p], wF2[p]);
                fma2(aG2, hp[p], wG2[p]);
                fma2(aO2, hp[p], wO2[p]);
            }
            float l0, h0, l1, h1, l2, h2, l3, h3;
            UNPACK2(l0, h0, aI2);
            UNPACK2(l1, h1, aF2);
            UNPACK2(l2, h2, aG2);
            UNPACK2(l3, h3, aO2);

            float ig = sigm_fast(l0 + h0);
            float fg = sigm_fast(l1 + h1);
            float gg = tanh_fast(l2 + h2);
            float og = sigm_fast(l3 + h3);
            c = fmaf(fg, c, ig * gg);
            h = og * tanh_fast(c);

            hsm[(tt + 1) & 1][warp][slot] = h;   // publish for step t+1
            __syncwarp();

            if (valid)
                __stcs(&outp[(size_t)tt * HH], h);
        }
    }

    if (valid)
        out[(size_t)BB * TT * HH + (size_t)b * HH + j] = h;
}

// ---------------------------------------------------------------------------
extern "C" void kernel_launch(void* const* d_in, const int* in_sizes, int n_in,
                              void* d_out, int out_size)
{
    const float* x    = (const float*)d_in[0];
    const float* W_ih = (const float*)d_in[1];
    const float* W_hh = (const float*)d_in[2];
    const float* b_ih = (const float*)d_in[3];
    const float* b_hh = (const float*)d_in[4];
    float* out = (float*)d_out;

    // K1: 16384 CTAs of 128 rows, split x4 so ncu's capture window sees K1
    const int total_blocks = (BB * TT) / 128;      // 16384
    const int q = total_blocks / 4;                // 4096
    for (int i = 0; i < 4; ++i)
        input_proj_kernel<<<q, 256>>>(x, W_ih, b_ih, b_hh, i * q);

    int grid2 = (BB + K2_BATCH_PER_BLOCK - 1) / K2_BATCH_PER_BLOCK;  // 683
    lstm_scan_kernel<<<grid2, K2_THREADS>>>(W_hh, out);
}

// round 6
// speedup vs baseline: 1.0978x; 1.0978x over previous
#include <cuda_runtime.h>
#include <cstdint>

#define BB 4096
#define TT 512
#define IND 64
#define HH 10

// 335.5 MB scratch: permuted layout idx = bt*40 + j*4 + gate (0=i 1=f 2=g 3=o)
__device__ float xg_buf[(size_t)BB * TT * 40];

__device__ __forceinline__ void fma2(unsigned long long& d,
                                     unsigned long long a,
                                     unsigned long long b) {
    asm("fma.rn.f32x2 %0, %1, %2, %0;" : "+l"(d) : "l"(a), "l"(b));
}
#define UNPACK2(lo, hi, s) \
    asm("mov.b64 {%0, %1}, %2;" : "=f"(lo), "=f"(hi) : "l"(s))

// ---------------------------------------------------------------------------
// K1: [2M x 64] * [64 x 40] + bias.  256 threads, 128 rows/block.
// Warp w owns gate group g0=w*5 (weight LDS = warp-uniform broadcast).
// Lane covers rows i*32+lane (i=0..3): x LDS phase-conflict-free (pad 17).
// Thread tile 4 rows x 5 gates, f32x2 packed FMA -> FMA2-pipe bound.
// ---------------------------------------------------------------------------
__global__ __launch_bounds__(256, 3)
void input_proj_kernel(const float* __restrict__ x,
                       const float* __restrict__ W_ih,
                       const float* __restrict__ b_ih,
                       const float* __restrict__ b_hh,
                       int block0)
{
    __shared__ __align__(16) float4 xs[128][17];   // 128 rows x 16 f4 (+pad)
    __shared__ __align__(16) float4 ws[40][17];    // 40 gates x 16 f4 (+pad)

    const int tid  = threadIdx.x;
    const int lane = tid & 31;
    const int wid  = tid >> 5;                     // 0..7
    const size_t row0 = (size_t)(blockIdx.x + block0) * 128;

    const float4* x4 = (const float4*)(x + row0 * IND);
    #pragma unroll
    for (int i = tid; i < 2048; i += 256)
        xs[i >> 4][i & 15] = __ldcs(&x4[i]);
    const float4* w4 = (const float4*)W_ih;
    #pragma unroll
    for (int i = tid; i < 640; i += 256)
        ws[i >> 4][i & 15] = w4[i];
    __syncthreads();

    const int g0 = wid * 5;                        // warp-uniform gate group

    float bsum[5];
    #pragma unroll
    for (int g = 0; g < 5; ++g)
        bsum[g] = b_ih[g0 + g] + b_hh[g0 + g];

    unsigned long long acc[4][5];
    #pragma unroll
    for (int r = 0; r < 4; ++r)
        #pragma unroll
        for (int g = 0; g < 5; ++g)
            acc[r][g] = 0ull;

    #pragma unroll 4
    for (int kc = 0; kc < 16; ++kc) {
        float4 wb[5];                              // broadcast loads (uniform addr)
        #pragma unroll
        for (int g = 0; g < 5; ++g) wb[g] = ws[g0 + g][kc];

        #pragma unroll
        for (int r = 0; r < 4; ++r) {
            float4 xv = xs[r * 32 + lane][kc];     // conflict-free per phase
            const unsigned long long* xp = (const unsigned long long*)&xv;
            #pragma unroll
            for (int g = 0; g < 5; ++g) {
                const unsigned long long* wp = (const unsigned long long*)&wb[g];
                fma2(acc[r][g], xp[0], wp[0]);
                fma2(acc[r][g], xp[1], wp[1]);
            }
        }
    }

    // epilogue: reduce pairs, bias, permute to [j*4+gate], coalesced flush
    __syncthreads();
    float* osm = (float*)xs;    // 128 rows x 44 floats (11 f4, 16B-aligned)
    #pragma unroll
    for (int r = 0; r < 4; ++r) {
        const int row = r * 32 + lane;
        #pragma unroll
        for (int g = 0; g < 5; ++g) {
            float lo, hi;
            UNPACK2(lo, hi, acc[r][g]);
            float v = lo + hi + bsum[g];
            int gg = g0 + g;
            int j  = gg % 10;
            int gi = gg / 10;
            osm[row * 44 + j * 4 + gi] = v;
        }
    }
    __syncthreads();

    float4* dst = (float4*)(xg_buf + row0 * 40);
    const float4* src4 = (const float4*)osm;
    #pragma unroll
    for (int i = tid; i < 1280; i += 256) {
        int rr = i / 10, c = i - rr * 10;
        __stcs(&dst[i], src4[rr * 11 + c]);
    }
}

// ---------------------------------------------------------------------------
// K2: recurrent scan (reverted to proven R3 version, 128 us).
// 3 batches/warp (lanes 0..29), unit j = lane%10, h broadcast via shfl.
// ---------------------------------------------------------------------------
__device__ __forceinline__ float sigm_fast(float x) {
    return __fdividef(1.0f, 1.0f + __expf(-x));
}
__device__ __forceinline__ float tanh_fast(float x) {
    return 1.0f - 2.0f * __fdividef(1.0f, 1.0f + __expf(2.0f * x));
}

#define K2_THREADS 64
#define K2_BATCH_PER_BLOCK 6

__global__ __launch_bounds__(K2_THREADS, 1)
void lstm_scan_kernel(const float* __restrict__ W_hh,
                      float* __restrict__ out)
{
    const int lane = threadIdx.x & 31;
    const int warp = threadIdx.x >> 5;
    int group = lane / 10;
    const bool active = (lane < 30);
    if (!active) group = 2;
    const int j = active ? (lane - group * 10) : 0;

    const int b = blockIdx.x * K2_BATCH_PER_BLOCK + warp * 3 + group;
    const bool valid = active && (b < BB);
    const int b_eff = valid ? b : 0;

    float wI[10], wF[10], wG[10], wO[10];
    #pragma unroll
    for (int k = 0; k < 10; ++k) {
        wI[k] = W_hh[(j)      * HH + k];
        wF[k] = W_hh[(j + 10) * HH + k];
        wG[k] = W_hh[(j + 20) * HH + k];
        wO[k] = W_hh[(j + 30) * HH + k];
    }

    const float4* xgp = (const float4*)(xg_buf + (size_t)b_eff * TT * 40) + j;

    float4 pf[8];
    #pragma unroll
    for (int d = 0; d < 8; ++d)
        pf[d] = __ldcs(&xgp[(size_t)d * 10]);

    float h = 0.0f, c = 0.0f;
    float* outp = out + (size_t)b_eff * TT * HH + j;
    const int srcbase = group * 10;

    for (int t = 0; t < TT; t += 8) {
        #pragma unroll
        for (int u = 0; u < 8; ++u) {
            float4 xv = pf[u];
            int tn = t + u + 8;
            if (tn < TT)
                pf[u] = __ldcs(&xgp[(size_t)tn * 10]);

            float aI = xv.x, aF = xv.y, aG = xv.z, aO = xv.w;
            #pragma unroll
            for (int k = 0; k < 10; ++k) {
                float hk = __shfl_sync(0xffffffffu, h, srcbase + k);
                aI = fmaf(hk, wI[k], aI);
                aF = fmaf(hk, wF[k], aF);
                aG = fmaf(hk, wG[k], aG);
                aO = fmaf(hk, wO[k], aO);
            }
            float ig = sigm_fast(aI);
            float fg = sigm_fast(aF);
            float gg = tanh_fast(aG);
            float og = sigm_fast(aO);
            c = fmaf(fg, c, ig * gg);
            h = og * tanh_fast(c);

            if (valid)
                __stcs(&outp[(size_t)(t + u) * HH], h);
        }
    }

    if (valid)
        out[(size_t)BB * TT * HH + (size_t)b * HH + j] = h;
}

// ---------------------------------------------------------------------------
extern "C" void kernel_launch(void* const* d_in, const int* in_sizes, int n_in,
                              void* d_out, int out_size)
{
    const float* x    = (const float*)d_in[0];
    const float* W_ih = (const float*)d_in[1];
    const float* W_hh = (const float*)d_in[2];
    const float* b_ih = (const float*)d_in[3];
    const float* b_hh = (const float*)d_in[4];
    float* out = (float*)d_out;

    // K1: 16384 CTAs of 128 rows, split x4 so ncu's capture window sees K1
    const int total_blocks = (BB * TT) / 128;      // 16384
    const int q = total_blocks / 4;                // 4096
    for (int i = 0; i < 4; ++i)
        input_proj_kernel<<<q, 256>>>(x, W_ih, b_ih, b_hh, i * q);

    int grid2 = (BB + K2_BATCH_PER_BLOCK - 1) / K2_BATCH_PER_BLOCK;  // 683
    lstm_scan_kernel<<<grid2, K2_THREADS>>>(W_hh, out);
}